// round 1
// baseline (speedup 1.0000x reference)
#include <cuda_runtime.h>
#include <math.h>

// ---------------- problem constants ----------------
#define BATCH 4
#define LEN   21760          // Len_q == Len_in
#define DM    256            // d_model
#define NH    8              // heads
#define NL    4              // levels
#define NP    4              // points
#define DH    32             // head dim
#define NTOK  (BATCH * LEN)  // 87040
#define NATTN (NH * NL * NP) // 128

// ---------------- scratch (no allocs allowed) ----------------
__device__ float g_value[(size_t)NTOK * DM];   // value projection  [B*Lin, 256]
__device__ float g_soff [(size_t)NTOK * DM];   // sampling offsets  [B*Lq, 256]
__device__ float g_sattn[(size_t)NTOK * NATTN];// attn logits       [B*Lq, 128]
__device__ float g_t    [(size_t)NTOK * DM];   // attention output  [B*Lq, 256]

// ---------------- fp32 GEMM:  C[M,N] = A[M,K] @ B[K,N] + bias[N] ----------------
// M % 128 == 0, N % 64 == 0, K % 32 == 0 (all hold here)
#define BM 128
#define BN 64
#define BK 32
#define TM 8
#define TN 4

__global__ __launch_bounds__(256, 2)
void sgemm_bias(const float* __restrict__ A, const float* __restrict__ B,
                const float* __restrict__ bias, float* __restrict__ C,
                int M, int N, int K) {
    __shared__ float As[BK][BM + 4];   // +4 pad: conflict-free transposed stores, 16B-aligned reads
    __shared__ float Bs[BK][BN];

    const int bm = blockIdx.y * BM;
    const int bn = blockIdx.x * BN;
    const int tid = threadIdx.x;          // 0..255
    const int tx = tid & 15;              // N direction
    const int ty = tid >> 4;              // M direction

    // A loader: 128x32 tile, float4; 32 rows per pass, 4 passes
    const int ar  = tid >> 3;             // 0..31
    const int ac4 = tid & 7;              // float4 column within 32-wide K slab
    // B loader: 32x64 tile, float4; 16 rows per pass, 2 passes
    const int br  = tid >> 4;             // 0..15
    const int bc4 = tid & 15;             // float4 column within 64-wide N slab

    float acc[TM][TN];
    #pragma unroll
    for (int i = 0; i < TM; i++)
        #pragma unroll
        for (int j = 0; j < TN; j++) acc[i][j] = 0.f;

    for (int k0 = 0; k0 < K; k0 += BK) {
        #pragma unroll
        for (int i = 0; i < 4; i++) {
            const int mrow = ar + i * 32;
            float4 v = *(const float4*)&A[(size_t)(bm + mrow) * K + k0 + ac4 * 4];
            As[ac4 * 4 + 0][mrow] = v.x;
            As[ac4 * 4 + 1][mrow] = v.y;
            As[ac4 * 4 + 2][mrow] = v.z;
            As[ac4 * 4 + 3][mrow] = v.w;
        }
        #pragma unroll
        for (int i = 0; i < 2; i++) {
            const int kk = br + i * 16;
            *(float4*)&Bs[kk][bc4 * 4] =
                *(const float4*)&B[(size_t)(k0 + kk) * N + bn + bc4 * 4];
        }
        __syncthreads();

        #pragma unroll
        for (int k = 0; k < BK; k++) {
            float4 a0 = *(const float4*)&As[k][ty * TM];
            float4 a1 = *(const float4*)&As[k][ty * TM + 4];
            float4 bq = *(const float4*)&Bs[k][tx * TN];
            const float a[TM] = {a0.x, a0.y, a0.z, a0.w, a1.x, a1.y, a1.z, a1.w};
            const float b[TN] = {bq.x, bq.y, bq.z, bq.w};
            #pragma unroll
            for (int i = 0; i < TM; i++)
                #pragma unroll
                for (int j = 0; j < TN; j++) acc[i][j] += a[i] * b[j];
        }
        __syncthreads();
    }

    #pragma unroll
    for (int i = 0; i < TM; i++) {
        const int mrow = bm + ty * TM + i;
        #pragma unroll
        for (int j = 0; j < TN; j++) {
            const int ncol = bn + tx * TN + j;
            C[(size_t)mrow * N + ncol] = acc[i][j] + bias[ncol];
        }
    }
}

// ---------------- sampling kernel: one warp per (token, head) ----------------
__global__ __launch_bounds__(256)
void sample_kernel(const float* __restrict__ refp,   // [B, Lq, L, 2]
                   const int*   __restrict__ spatial,// [L, 2] = (H, W)
                   const int*   __restrict__ lstart) // [L]
{
    const int wid  = blockIdx.x * 8 + (threadIdx.x >> 5);
    const int lane = threadIdx.x & 31;
    if (wid >= NTOK * NH) return;
    const int m = wid & (NH - 1);
    const int t = wid >> 3;              // b*Lq + q
    const int b = t / LEN;

    const float* soff  = g_soff  + (size_t)t * DM    + m * (NL * NP * 2);
    const float* sattn = g_sattn + (size_t)t * NATTN + m * (NL * NP);
    const float* ref   = refp    + (size_t)t * (NL * 2);

    // softmax over the 16 (level, point) logits for this head
    float lg[NL * NP];
    float mx = -1e30f;
    #pragma unroll
    for (int i = 0; i < NL * NP; i++) { lg[i] = sattn[i]; mx = fmaxf(mx, lg[i]); }
    float ssum = 0.f;
    #pragma unroll
    for (int i = 0; i < NL * NP; i++) { lg[i] = expf(lg[i] - mx); ssum += lg[i]; }
    const float inv = 1.f / ssum;

    float acc = 0.f;
    #pragma unroll
    for (int l = 0; l < NL; l++) {
        const int   H  = spatial[l * 2 + 0];
        const int   W  = spatial[l * 2 + 1];
        const float Hf = (float)H, Wf = (float)W;
        const int start = lstart[l];
        const float rx = ref[l * 2 + 0];
        const float ry = ref[l * 2 + 1];
        const float* vbase =
            g_value + (((size_t)b * LEN + start) * NH + m) * DH + lane;
        #pragma unroll
        for (int p = 0; p < NP; p++) {
            const float ox = soff[l * (NP * 2) + p * 2 + 0];
            const float oy = soff[l * (NP * 2) + p * 2 + 1];
            // loc = ref + off / (W,H);  x = loc_x*W - 0.5, y = loc_y*H - 0.5
            const float x = (rx + ox / Wf) * Wf - 0.5f;
            const float y = (ry + oy / Hf) * Hf - 0.5f;
            const float x0f = floorf(x), y0f = floorf(y);
            const float fx = x - x0f, fy = y - y0f;
            const int x0 = (int)x0f, y0 = (int)y0f;
            const float w00 = (1.f - fx) * (1.f - fy);
            const float w01 = fx * (1.f - fy);
            const float w10 = (1.f - fx) * fy;
            const float w11 = fx * fy;
            float s = 0.f;
            if (y0 >= 0 && y0 < H) {
                const size_t row = (size_t)y0 * W;
                if (x0 >= 0 && x0 < W)         s += w00 * vbase[(row + x0)     * (NH * DH)];
                if (x0 + 1 >= 0 && x0 + 1 < W) s += w01 * vbase[(row + x0 + 1) * (NH * DH)];
            }
            if (y0 + 1 >= 0 && y0 + 1 < H) {
                const size_t row = (size_t)(y0 + 1) * W;
                if (x0 >= 0 && x0 < W)         s += w10 * vbase[(row + x0)     * (NH * DH)];
                if (x0 + 1 >= 0 && x0 + 1 < W) s += w11 * vbase[(row + x0 + 1) * (NH * DH)];
            }
            acc += (lg[l * NP + p] * inv) * s;
        }
    }
    g_t[(size_t)t * DM + m * DH + lane] = acc;
}

// ---------------- launch ----------------
extern "C" void kernel_launch(void* const* d_in, const int* in_sizes, int n_in,
                              void* d_out, int out_size) {
    const float* query  = (const float*)d_in[0];
    const float* refp   = (const float*)d_in[1];
    const float* xin    = (const float*)d_in[2];
    const int*   spatial= (const int*)  d_in[3];
    const int*   lstart = (const int*)  d_in[4];
    const float* W_off  = (const float*)d_in[5];
    const float* b_off  = (const float*)d_in[6];
    const float* W_attn = (const float*)d_in[7];
    const float* b_attn = (const float*)d_in[8];
    const float* W_val  = (const float*)d_in[9];
    const float* b_val  = (const float*)d_in[10];
    const float* W_out  = (const float*)d_in[11];
    const float* b_out  = (const float*)d_in[12];
    float* out = (float*)d_out;

    float *pv, *pso, *psa, *pt;
    cudaGetSymbolAddress((void**)&pv,  g_value);
    cudaGetSymbolAddress((void**)&pso, g_soff);
    cudaGetSymbolAddress((void**)&psa, g_sattn);
    cudaGetSymbolAddress((void**)&pt,  g_t);

    dim3 blk(256);
    dim3 g256(DM / BN, NTOK / BM);      // N=256
    dim3 g128(128 / BN, NTOK / BM);     // N=128

    sgemm_bias<<<g256, blk>>>(xin,   W_val,  b_val,  pv,  NTOK, DM,  DM);
    sgemm_bias<<<g256, blk>>>(query, W_off,  b_off,  pso, NTOK, DM,  DM);
    sgemm_bias<<<g128, blk>>>(query, W_attn, b_attn, psa, NTOK, 128, DM);
    sample_kernel<<<NTOK, 256>>>(refp, spatial, lstart);
    sgemm_bias<<<g256, blk>>>(pt,    W_out,  b_out,  out, NTOK, DM,  DM);
}

// round 2
// speedup vs baseline: 1.4212x; 1.4212x over previous
#include <cuda_runtime.h>
#include <math.h>

// ---------------- problem constants ----------------
#define BATCH 4
#define LEN   21760          // Len_q == Len_in
#define DM    256            // d_model
#define NH    8              // heads
#define NL    4              // levels
#define NP    4              // points
#define DH    32             // head dim
#define NTOK  (BATCH * LEN)  // 87040
#define NATTN (NH * NL * NP) // 128
#define NPTS  (NL * NP)      // 16 points per (token, head)

// ---------------- scratch (no allocs allowed) ----------------
__device__ float g_value[(size_t)NTOK * DM];    // value projection  [B*Lin, 256]
__device__ float g_soff [(size_t)NTOK * DM];    // sampling offsets  [B*Lq, 256]
__device__ float g_sattn[(size_t)NTOK * NATTN]; // attn logits       [B*Lq, 128]
__device__ float g_t    [(size_t)NTOK * DM];    // attention output  [B*Lq, 256]
// per (token, head, point): 4 gather indices (u16, within-batch token id) + 4 fused weights
__device__ unsigned short g_pidx[(size_t)NTOK * NH * NPTS * 4];
__device__ float          g_pw  [(size_t)NTOK * NH * NPTS * 4];

// ---------------- fp32 GEMM:  C[M,N] = A[M,K] @ B[K,N] + bias[N] ----------------
#define BM 128
#define BN 64
#define BK 32
#define TM 8
#define TN 4

__global__ __launch_bounds__(256, 2)
void sgemm_bias(const float* __restrict__ A, const float* __restrict__ B,
                const float* __restrict__ bias, float* __restrict__ C,
                int M, int N, int K) {
    __shared__ float As[BK][BM + 4];
    __shared__ float Bs[BK][BN];

    const int bm = blockIdx.y * BM;
    const int bn = blockIdx.x * BN;
    const int tid = threadIdx.x;
    const int tx = tid & 15;
    const int ty = tid >> 4;

    const int ar  = tid >> 3;
    const int ac4 = tid & 7;
    const int br  = tid >> 4;
    const int bc4 = tid & 15;

    float acc[TM][TN];
    #pragma unroll
    for (int i = 0; i < TM; i++)
        #pragma unroll
        for (int j = 0; j < TN; j++) acc[i][j] = 0.f;

    for (int k0 = 0; k0 < K; k0 += BK) {
        #pragma unroll
        for (int i = 0; i < 4; i++) {
            const int mrow = ar + i * 32;
            float4 v = *(const float4*)&A[(size_t)(bm + mrow) * K + k0 + ac4 * 4];
            As[ac4 * 4 + 0][mrow] = v.x;
            As[ac4 * 4 + 1][mrow] = v.y;
            As[ac4 * 4 + 2][mrow] = v.z;
            As[ac4 * 4 + 3][mrow] = v.w;
        }
        #pragma unroll
        for (int i = 0; i < 2; i++) {
            const int kk = br + i * 16;
            *(float4*)&Bs[kk][bc4 * 4] =
                *(const float4*)&B[(size_t)(k0 + kk) * N + bn + bc4 * 4];
        }
        __syncthreads();

        #pragma unroll
        for (int k = 0; k < BK; k++) {
            float4 a0 = *(const float4*)&As[k][ty * TM];
            float4 a1 = *(const float4*)&As[k][ty * TM + 4];
            float4 bq = *(const float4*)&Bs[k][tx * TN];
            const float a[TM] = {a0.x, a0.y, a0.z, a0.w, a1.x, a1.y, a1.z, a1.w};
            const float b[TN] = {bq.x, bq.y, bq.z, bq.w};
            #pragma unroll
            for (int i = 0; i < TM; i++)
                #pragma unroll
                for (int j = 0; j < TN; j++) acc[i][j] += a[i] * b[j];
        }
        __syncthreads();
    }

    #pragma unroll
    for (int i = 0; i < TM; i++) {
        const int mrow = bm + ty * TM + i;
        #pragma unroll
        for (int j = 0; j < TN; j++) {
            const int ncol = bn + tx * TN + j;
            C[(size_t)mrow * N + ncol] = acc[i][j] + bias[ncol];
        }
    }
}

// ---------------- precompute: one thread per (token, head) ----------------
// Does softmax + point/corner math ONCE (not 32x per warp) and emits fused
// (index, weight) pairs: weight = attn_w * bilinear_w * validity.
__global__ __launch_bounds__(256)
void precompute_kernel(const float* __restrict__ refp,    // [B, Lq, L, 2]
                       const int*   __restrict__ spatial, // [L, 2] = (H, W)
                       const int*   __restrict__ lstart)  // [L]
{
    const int tm = blockIdx.x * blockDim.x + threadIdx.x;  // t*NH + m
    if (tm >= NTOK * NH) return;
    const int m = tm & (NH - 1);
    const int t = tm >> 3;

    // softmax over 16 logits
    const float* sattn = g_sattn + (size_t)t * NATTN + m * NPTS;
    float lg[NPTS];
    float mx = -1e30f;
    #pragma unroll
    for (int i = 0; i < NPTS; i++) { lg[i] = sattn[i]; mx = fmaxf(mx, lg[i]); }
    float ssum = 0.f;
    #pragma unroll
    for (int i = 0; i < NPTS; i++) { lg[i] = __expf(lg[i] - mx); ssum += lg[i]; }
    const float inv = 1.f / ssum;

    const float* ref  = refp   + (size_t)t * (NL * 2);
    const float* soff = g_soff + (size_t)t * DM + m * (NL * NP * 2);
    ushort4* opid = (ushort4*)g_pidx + (size_t)tm * NPTS;
    float4*  opw  = (float4*) g_pw   + (size_t)tm * NPTS;

    #pragma unroll
    for (int l = 0; l < NL; l++) {
        const int   H  = spatial[l * 2 + 0];
        const int   W  = spatial[l * 2 + 1];
        const float Hf = (float)H, Wf = (float)W;
        const int start = lstart[l];
        const float rx = ref[l * 2 + 0];
        const float ry = ref[l * 2 + 1];
        #pragma unroll
        for (int p = 0; p < NP; p++) {
            const float ox = soff[l * (NP * 2) + p * 2 + 0];
            const float oy = soff[l * (NP * 2) + p * 2 + 1];
            const float x = (rx + ox / Wf) * Wf - 0.5f;
            const float y = (ry + oy / Hf) * Hf - 0.5f;
            const float x0f = floorf(x), y0f = floorf(y);
            const float fx = x - x0f, fy = y - y0f;
            const int x0 = (int)x0f, y0 = (int)y0f;
            const int x1 = x0 + 1,   y1 = y0 + 1;
            const float aw = lg[l * NP + p] * inv;

            const bool vx0 = (x0 >= 0) & (x0 < W);
            const bool vx1 = (x1 >= 0) & (x1 < W);
            const bool vy0 = (y0 >= 0) & (y0 < H);
            const bool vy1 = (y1 >= 0) & (y1 < H);

            ushort4 i4;
            float4  w4;
            i4.x = (vy0 && vx0) ? (unsigned short)(start + y0 * W + x0) : 0;
            i4.y = (vy0 && vx1) ? (unsigned short)(start + y0 * W + x1) : 0;
            i4.z = (vy1 && vx0) ? (unsigned short)(start + y1 * W + x0) : 0;
            i4.w = (vy1 && vx1) ? (unsigned short)(start + y1 * W + x1) : 0;
            w4.x = (vy0 && vx0) ? aw * (1.f - fx) * (1.f - fy) : 0.f;
            w4.y = (vy0 && vx1) ? aw * fx * (1.f - fy)         : 0.f;
            w4.z = (vy1 && vx0) ? aw * (1.f - fx) * fy         : 0.f;
            w4.w = (vy1 && vx1) ? aw * fx * fy                 : 0.f;

            opid[l * NP + p] = i4;
            opw [l * NP + p] = w4;
        }
    }
}

// ---------------- gather: one warp per (token, head), pure streaming ----------------
// Block = 8 warps = 8 ADJACENT TOKENS of the SAME head (L1 reuse on value rows).
__global__ __launch_bounds__(256)
void sample_kernel() {
    const int warp = threadIdx.x >> 5;
    const int lane = threadIdx.x & 31;
    const int blk  = blockIdx.x;
    const int m = blk & (NH - 1);
    const int t = (blk >> 3) * 8 + warp;
    const int b = t / LEN;

    const float* vbase =
        g_value + (size_t)b * LEN * DM + m * DH + lane;
    const ushort4* pidx = (const ushort4*)g_pidx + ((size_t)t * NH + m) * NPTS;
    const float4*  pw   = (const float4*) g_pw   + ((size_t)t * NH + m) * NPTS;

    float acc = 0.f;
    #pragma unroll
    for (int pp = 0; pp < NPTS; pp++) {
        const ushort4 i4 = pidx[pp];
        const float4  w4 = pw[pp];
        acc += w4.x * vbase[(int)i4.x * DM];
        acc += w4.y * vbase[(int)i4.y * DM];
        acc += w4.z * vbase[(int)i4.z * DM];
        acc += w4.w * vbase[(int)i4.w * DM];
    }
    g_t[(size_t)t * DM + m * DH + lane] = acc;
}

// ---------------- launch ----------------
extern "C" void kernel_launch(void* const* d_in, const int* in_sizes, int n_in,
                              void* d_out, int out_size) {
    const float* query  = (const float*)d_in[0];
    const float* refp   = (const float*)d_in[1];
    const float* xin    = (const float*)d_in[2];
    const int*   spatial= (const int*)  d_in[3];
    const int*   lstart = (const int*)  d_in[4];
    const float* W_off  = (const float*)d_in[5];
    const float* b_off  = (const float*)d_in[6];
    const float* W_attn = (const float*)d_in[7];
    const float* b_attn = (const float*)d_in[8];
    const float* W_val  = (const float*)d_in[9];
    const float* b_val  = (const float*)d_in[10];
    const float* W_out  = (const float*)d_in[11];
    const float* b_out  = (const float*)d_in[12];
    float* out = (float*)d_out;

    float *pv, *pso, *psa, *pt;
    cudaGetSymbolAddress((void**)&pv,  g_value);
    cudaGetSymbolAddress((void**)&pso, g_soff);
    cudaGetSymbolAddress((void**)&psa, g_sattn);
    cudaGetSymbolAddress((void**)&pt,  g_t);

    dim3 blk(256);
    dim3 g256(DM / BN, NTOK / BM);      // N=256
    dim3 g128(128 / BN, NTOK / BM);     // N=128

    sgemm_bias<<<g256, blk>>>(xin,   W_val,  b_val,  pv,  NTOK, DM,  DM);
    sgemm_bias<<<g256, blk>>>(query, W_off,  b_off,  pso, NTOK, DM,  DM);
    sgemm_bias<<<g128, blk>>>(query, W_attn, b_attn, psa, NTOK, 128, DM);
    precompute_kernel<<<(NTOK * NH + 255) / 256, 256>>>(refp, spatial, lstart);
    sample_kernel<<<NTOK, 256>>>();
    sgemm_bias<<<g256, blk>>>(pt,    W_out,  b_out,  out, NTOK, DM,  DM);
}

// round 5
// speedup vs baseline: 2.1413x; 1.5067x over previous
#include <cuda_runtime.h>
#include <math.h>
#include <stdint.h>

// ---------------- problem constants ----------------
#define BATCH 4
#define LEN   21760
#define DM    256
#define NH    8
#define NL    4
#define NP    4
#define DH    32
#define NTOK  (BATCH * LEN)  // 87040
#define NATTN (NH * NL * NP) // 128
#define NPTS  (NL * NP)      // 16

// ---------------- scratch ----------------
__device__ float g_value[(size_t)NTOK * DM];
__device__ float g_soff [(size_t)NTOK * DM];
__device__ float g_sattn[(size_t)NTOK * NATTN];
__device__ float g_t    [(size_t)NTOK * DM];
__device__ unsigned short g_pidx[(size_t)NTOK * NH * NPTS * 4];
__device__ float          g_pw  [(size_t)NTOK * NH * NPTS * 4];
// transposed weights [N, K] (K-major)
__device__ float g_WvalT [DM * DM];
__device__ float g_WoffT [DM * DM];
__device__ float g_WattnT[NATTN * DM];
__device__ float g_WoutT [DM * DM];

// ---------------- tf32 helpers ----------------
__device__ __forceinline__ float to_tf32(float x) {
    float y;
    asm("cvt.rna.tf32.f32 %0, %1;" : "=f"(y) : "f"(x));
    return y;
}

__device__ __forceinline__ void mma_tf32(float c[4], const float a[4], const float b[2]) {
    asm volatile(
        "mma.sync.aligned.m16n8k8.row.col.f32.tf32.tf32.f32 "
        "{%0,%1,%2,%3}, {%4,%5,%6,%7}, {%8,%9}, {%0,%1,%2,%3};"
        : "+f"(c[0]), "+f"(c[1]), "+f"(c[2]), "+f"(c[3])
        : "f"(a[0]), "f"(a[1]), "f"(a[2]), "f"(a[3]), "f"(b[0]), "f"(b[1]));
}

// ---------------- tf32 mma.sync GEMM ----------------
// C[M,N] = A[M,K] @ Bt[N,K]^T + bias[N]
// 256 threads = 8 warps (4 x 2). BM=128, BN=64, BK=32. Warp tile 32x32.
#define GBM 128
#define GBN 64
#define GBK 32
#define APAD 4
#define ASTR (GBK + APAD)   // 36

__global__ __launch_bounds__(256, 2)
void tf32_gemm(const float* __restrict__ A, const float* __restrict__ Bt,
               const float* __restrict__ bias, float* __restrict__ C,
               int M, int N, int K) {
    __shared__ float As[GBM][ASTR];
    __shared__ float Bs[GBN][ASTR];

    const int tid  = threadIdx.x;
    const int lane = tid & 31;
    const int wid  = tid >> 5;
    const int wm   = wid & 3;       // 0..3 (m direction)
    const int wn   = wid >> 2;      // 0..1 (n direction)
    const int bm = blockIdx.x * GBM;
    const int bn = blockIdx.y * GBN;

    const int grp = lane >> 2;      // 0..7
    const int tig = lane & 3;       // 0..3

    float acc[2][4][4];
    #pragma unroll
    for (int i = 0; i < 2; i++)
        #pragma unroll
        for (int j = 0; j < 4; j++)
            #pragma unroll
            for (int r = 0; r < 4; r++) acc[i][j][r] = 0.f;

    for (int k0 = 0; k0 < K; k0 += GBK) {
        // load A tile: 128 x 32 floats (1024 float4, 4 per thread), tf32-round
        #pragma unroll
        for (int i = 0; i < 4; i++) {
            const int f   = tid + i * 256;
            const int row = f >> 3;
            const int c4  = f & 7;
            float4 v = *(const float4*)&A[(size_t)(bm + row) * K + k0 + c4 * 4];
            v.x = to_tf32(v.x); v.y = to_tf32(v.y);
            v.z = to_tf32(v.z); v.w = to_tf32(v.w);
            *(float4*)&As[row][c4 * 4] = v;
        }
        // load B tile: 64 x 32 floats (512 float4, 2 per thread)
        #pragma unroll
        for (int i = 0; i < 2; i++) {
            const int f   = tid + i * 256;
            const int row = f >> 3;
            const int c4  = f & 7;
            float4 v = *(const float4*)&Bt[(size_t)(bn + row) * K + k0 + c4 * 4];
            v.x = to_tf32(v.x); v.y = to_tf32(v.y);
            v.z = to_tf32(v.z); v.w = to_tf32(v.w);
            *(float4*)&Bs[row][c4 * 4] = v;
        }
        __syncthreads();

        #pragma unroll
        for (int ks = 0; ks < 4; ks++) {
            const int kc = ks * 8;
            float a[2][4];
            #pragma unroll
            for (int mt = 0; mt < 2; mt++) {
                const int r = wm * 32 + mt * 16 + grp;
                a[mt][0] = As[r    ][kc + tig];
                a[mt][1] = As[r + 8][kc + tig];
                a[mt][2] = As[r    ][kc + tig + 4];
                a[mt][3] = As[r + 8][kc + tig + 4];
            }
            float b[4][2];
            #pragma unroll
            for (int nt = 0; nt < 4; nt++) {
                const int n0 = wn * 32 + nt * 8 + grp;
                b[nt][0] = Bs[n0][kc + tig];
                b[nt][1] = Bs[n0][kc + tig + 4];
            }
            #pragma unroll
            for (int mt = 0; mt < 2; mt++)
                #pragma unroll
                for (int nt = 0; nt < 4; nt++)
                    mma_tf32(acc[mt][nt], a[mt], b[nt]);
        }
        __syncthreads();
    }

    // epilogue: c0:(row=grp, col=2*tig), c1:+1 col, c2/c3: row+8
    #pragma unroll
    for (int mt = 0; mt < 2; mt++) {
        #pragma unroll
        for (int nt = 0; nt < 4; nt++) {
            const int r0 = bm + wm * 32 + mt * 16 + grp;
            const int c0 = bn + wn * 32 + nt * 8 + tig * 2;
            const float b0 = bias[c0], b1 = bias[c0 + 1];
            float2 v0 = {acc[mt][nt][0] + b0, acc[mt][nt][1] + b1};
            float2 v1 = {acc[mt][nt][2] + b0, acc[mt][nt][3] + b1};
            *(float2*)&C[(size_t)r0 * N + c0]       = v0;
            *(float2*)&C[(size_t)(r0 + 8) * N + c0] = v1;
        }
    }
}

// ---------------- weight transpose: W[K,N] -> Wt[N,K] ----------------
__global__ void transpose_kernel(const float* __restrict__ W, float* __restrict__ Wt,
                                 int K, int N) {
    __shared__ float tile[32][33];
    const int n0 = blockIdx.x * 32, k0 = blockIdx.y * 32;
    for (int j = threadIdx.y; j < 32; j += 8)
        tile[j][threadIdx.x] = W[(size_t)(k0 + j) * N + n0 + threadIdx.x];
    __syncthreads();
    for (int j = threadIdx.y; j < 32; j += 8)
        Wt[(size_t)(n0 + j) * K + k0 + threadIdx.x] = tile[threadIdx.x][j];
}

// ---------------- precompute: one thread per (token, head) ----------------
__global__ __launch_bounds__(256)
void precompute_kernel(const float* __restrict__ refp,
                       const int*   __restrict__ spatial,
                       const int*   __restrict__ lstart) {
    const int tm = blockIdx.x * blockDim.x + threadIdx.x;
    if (tm >= NTOK * NH) return;
    const int m = tm & (NH - 1);
    const int t = tm >> 3;

    const float* sattn = g_sattn + (size_t)t * NATTN + m * NPTS;
    float lg[NPTS];
    float mx = -1e30f;
    #pragma unroll
    for (int i = 0; i < NPTS; i++) { lg[i] = sattn[i]; mx = fmaxf(mx, lg[i]); }
    float ssum = 0.f;
    #pragma unroll
    for (int i = 0; i < NPTS; i++) { lg[i] = __expf(lg[i] - mx); ssum += lg[i]; }
    const float inv = 1.f / ssum;

    const float* ref  = refp   + (size_t)t * (NL * 2);
    const float* soff = g_soff + (size_t)t * DM + m * (NL * NP * 2);
    ushort4* opid = (ushort4*)g_pidx + (size_t)tm * NPTS;
    float4*  opw  = (float4*) g_pw   + (size_t)tm * NPTS;

    #pragma unroll
    for (int l = 0; l < NL; l++) {
        const int   H  = spatial[l * 2 + 0];
        const int   W  = spatial[l * 2 + 1];
        const float Hf = (float)H, Wf = (float)W;
        const int start = lstart[l];
        const float rx = ref[l * 2 + 0];
        const float ry = ref[l * 2 + 1];
        #pragma unroll
        for (int p = 0; p < NP; p++) {
            const float ox = soff[l * (NP * 2) + p * 2 + 0];
            const float oy = soff[l * (NP * 2) + p * 2 + 1];
            const float x = (rx + ox / Wf) * Wf - 0.5f;
            const float y = (ry + oy / Hf) * Hf - 0.5f;
            const float x0f = floorf(x), y0f = floorf(y);
            const float fx = x - x0f, fy = y - y0f;
            const int x0 = (int)x0f, y0 = (int)y0f;
            const int x1 = x0 + 1,   y1 = y0 + 1;
            const float aw = lg[l * NP + p] * inv;

            const bool vx0 = (x0 >= 0) & (x0 < W);
            const bool vx1 = (x1 >= 0) & (x1 < W);
            const bool vy0 = (y0 >= 0) & (y0 < H);
            const bool vy1 = (y1 >= 0) & (y1 < H);

            ushort4 i4; float4 w4;
            i4.x = (vy0 && vx0) ? (unsigned short)(start + y0 * W + x0) : 0;
            i4.y = (vy0 && vx1) ? (unsigned short)(start + y0 * W + x1) : 0;
            i4.z = (vy1 && vx0) ? (unsigned short)(start + y1 * W + x0) : 0;
            i4.w = (vy1 && vx1) ? (unsigned short)(start + y1 * W + x1) : 0;
            w4.x = (vy0 && vx0) ? aw * (1.f - fx) * (1.f - fy) : 0.f;
            w4.y = (vy0 && vx1) ? aw * fx * (1.f - fy)         : 0.f;
            w4.z = (vy1 && vx0) ? aw * (1.f - fx) * fy         : 0.f;
            w4.w = (vy1 && vx1) ? aw * fx * fy                 : 0.f;

            opid[l * NP + p] = i4;
            opw [l * NP + p] = w4;
        }
    }
}

// ---------------- gather ----------------
__global__ __launch_bounds__(256)
void sample_kernel() {
    const int warp = threadIdx.x >> 5;
    const int lane = threadIdx.x & 31;
    const int blk  = blockIdx.x;
    const int m = blk & (NH - 1);
    const int t = (blk >> 3) * 8 + warp;
    const int b = t / LEN;

    const float* vbase = g_value + (size_t)b * LEN * DM + m * DH + lane;
    const ushort4* pidx = (const ushort4*)g_pidx + ((size_t)t * NH + m) * NPTS;
    const float4*  pw   = (const float4*) g_pw   + ((size_t)t * NH + m) * NPTS;

    float acc = 0.f;
    #pragma unroll
    for (int pp = 0; pp < NPTS; pp++) {
        const ushort4 i4 = pidx[pp];
        const float4  w4 = pw[pp];
        acc += w4.x * vbase[(int)i4.x * DM];
        acc += w4.y * vbase[(int)i4.y * DM];
        acc += w4.z * vbase[(int)i4.z * DM];
        acc += w4.w * vbase[(int)i4.w * DM];
    }
    g_t[(size_t)t * DM + m * DH + lane] = acc;
}

// ---------------- launch ----------------
extern "C" void kernel_launch(void* const* d_in, const int* in_sizes, int n_in,
                              void* d_out, int out_size) {
    const float* query  = (const float*)d_in[0];
    const float* refp   = (const float*)d_in[1];
    const float* xin    = (const float*)d_in[2];
    const int*   spatial= (const int*)  d_in[3];
    const int*   lstart = (const int*)  d_in[4];
    const float* W_off  = (const float*)d_in[5];
    const float* b_off  = (const float*)d_in[6];
    const float* W_attn = (const float*)d_in[7];
    const float* b_attn = (const float*)d_in[8];
    const float* W_val  = (const float*)d_in[9];
    const float* b_val  = (const float*)d_in[10];
    const float* W_out  = (const float*)d_in[11];
    const float* b_out  = (const float*)d_in[12];
    float* out = (float*)d_out;

    float *pv, *pso, *psa, *pt, *wvT, *woT, *waT, *wuT;
    cudaGetSymbolAddress((void**)&pv,  g_value);
    cudaGetSymbolAddress((void**)&pso, g_soff);
    cudaGetSymbolAddress((void**)&psa, g_sattn);
    cudaGetSymbolAddress((void**)&pt,  g_t);
    cudaGetSymbolAddress((void**)&wvT, g_WvalT);
    cudaGetSymbolAddress((void**)&woT, g_WoffT);
    cudaGetSymbolAddress((void**)&waT, g_WattnT);
    cudaGetSymbolAddress((void**)&wuT, g_WoutT);

    dim3 tb(32, 8);
    transpose_kernel<<<dim3(DM / 32,    DM / 32), tb>>>(W_val,  wvT, DM, DM);
    transpose_kernel<<<dim3(DM / 32,    DM / 32), tb>>>(W_off,  woT, DM, DM);
    transpose_kernel<<<dim3(NATTN / 32, DM / 32), tb>>>(W_attn, waT, DM, NATTN);
    transpose_kernel<<<dim3(DM / 32,    DM / 32), tb>>>(W_out,  wuT, DM, DM);

    const int mt = NTOK / GBM;   // 680
    tf32_gemm<<<dim3(mt, DM / GBN),    256>>>(xin,   wvT, b_val,  pv,  NTOK, DM,    DM);
    tf32_gemm<<<dim3(mt, DM / GBN),    256>>>(query, woT, b_off,  pso, NTOK, DM,    DM);
    tf32_gemm<<<dim3(mt, NATTN / GBN), 256>>>(query, waT, b_attn, psa, NTOK, NATTN, DM);

    precompute_kernel<<<(NTOK * NH + 255) / 256, 256>>>(refp, spatial, lstart);
    sample_kernel<<<NTOK, 256>>>();

    tf32_gemm<<<dim3(mt, DM / GBN), 256>>>(pt, wuT, b_out, out, NTOK, DM, DM);
}

// round 6
// speedup vs baseline: 2.1992x; 1.0270x over previous
#include <cuda_runtime.h>
#include <cuda_fp16.h>
#include <math.h>
#include <stdint.h>

// ---------------- problem constants ----------------
#define BATCH 4
#define LEN   21760
#define DM    256
#define NH    8
#define NL    4
#define NP    4
#define DH    32
#define NTOK  (BATCH * LEN)  // 87040
#define NATTN (NH * NL * NP) // 128
#define NPTS  (NL * NP)      // 16
#define TMN   ((size_t)NTOK * NH) // 696320

// ---------------- scratch ----------------
__device__ __half g_value[(size_t)NTOK * DM];   // value projection, fp16
__device__ float  g_soff [(size_t)NTOK * DM];
__device__ float  g_sattn[(size_t)NTOK * NATTN];
__device__ float  g_t    [(size_t)NTOK * DM];
// point-major: [pp][tm]
__device__ unsigned short g_pidx[NPTS * TMN * 4];
__device__ float          g_pw  [NPTS * TMN * 4];
// transposed weights [N, K] (K-major), fp16
__device__ __half g_WvalT [DM * DM];
__device__ __half g_WoffT [DM * DM];
__device__ __half g_WattnT[NATTN * DM];
__device__ __half g_WoutT [DM * DM];

// ---------------- fp16 mma ----------------
__device__ __forceinline__ void mma_f16(float c[4],
                                        uint32_t a0, uint32_t a1, uint32_t a2, uint32_t a3,
                                        uint32_t b0, uint32_t b1) {
    asm volatile(
        "mma.sync.aligned.m16n8k16.row.col.f32.f16.f16.f32 "
        "{%0,%1,%2,%3}, {%4,%5,%6,%7}, {%8,%9}, {%0,%1,%2,%3};"
        : "+f"(c[0]), "+f"(c[1]), "+f"(c[2]), "+f"(c[3])
        : "r"(a0), "r"(a1), "r"(a2), "r"(a3), "r"(b0), "r"(b1));
}

// ---------------- fp16 mma.sync GEMM ----------------
// C[M,N] = A[M,K] @ Bt[N,K]^T + bias[N];  A fp32, Bt fp16.
// Writes fp32 C, or fp16 Ch if Ch != nullptr.
// 256 threads = 8 warps (4 x 2). BM=128, BN=64, BK=32. Warp tile 32x32.
#define GBM 128
#define GBN 64
#define GBK 32
#define HSTR (GBK + 8)   // 40 halves: conflict-free half2 reads

__global__ __launch_bounds__(256, 2)
void f16_gemm(const float* __restrict__ A, const __half* __restrict__ Bt,
              const float* __restrict__ bias, float* __restrict__ C,
              __half* __restrict__ Ch, int M, int N, int K) {
    __shared__ __half As[GBM][HSTR];
    __shared__ __half Bs[GBN][HSTR];

    const int tid  = threadIdx.x;
    const int lane = tid & 31;
    const int wid  = tid >> 5;
    const int wm   = wid & 3;
    const int wn   = wid >> 2;
    const int bm = blockIdx.x * GBM;
    const int bn = blockIdx.y * GBN;
    const int grp = lane >> 2;
    const int tig = lane & 3;

    float acc[2][4][4];
    #pragma unroll
    for (int i = 0; i < 2; i++)
        #pragma unroll
        for (int j = 0; j < 4; j++)
            #pragma unroll
            for (int r = 0; r < 4; r++) acc[i][j][r] = 0.f;

    for (int k0 = 0; k0 < K; k0 += GBK) {
        // A: 128x32 fp32 -> fp16 smem. 1024 float4, 4/thread.
        #pragma unroll
        for (int i = 0; i < 4; i++) {
            const int f   = tid + i * 256;
            const int row = f >> 3;
            const int c4  = f & 7;
            float4 v = *(const float4*)&A[(size_t)(bm + row) * K + k0 + c4 * 4];
            __half2 h01 = __floats2half2_rn(v.x, v.y);
            __half2 h23 = __floats2half2_rn(v.z, v.w);
            uint2 u;
            u.x = *(uint32_t*)&h01;
            u.y = *(uint32_t*)&h23;
            *(uint2*)&As[row][c4 * 4] = u;
        }
        // B: 64x32 fp16. 2048 halves = 256 uint4-worth; do 2x uint2 per thread.
        {
            const int row = tid >> 2;      // 0..63
            const int c8  = tid & 3;       // 8-half group
            const uint2* src = (const uint2*)&Bt[(size_t)(bn + row) * K + k0 + c8 * 8];
            uint2 u0 = src[0];
            uint2 u1 = src[1];
            *(uint2*)&Bs[row][c8 * 8]     = u0;
            *(uint2*)&Bs[row][c8 * 8 + 4] = u1;
        }
        __syncthreads();

        #pragma unroll
        for (int kc = 0; kc < GBK; kc += 16) {
            uint32_t ra[2][4];
            #pragma unroll
            for (int mt = 0; mt < 2; mt++) {
                const int r = wm * 32 + mt * 16 + grp;
                ra[mt][0] = *(const uint32_t*)&As[r    ][kc + tig * 2];
                ra[mt][1] = *(const uint32_t*)&As[r + 8][kc + tig * 2];
                ra[mt][2] = *(const uint32_t*)&As[r    ][kc + tig * 2 + 8];
                ra[mt][3] = *(const uint32_t*)&As[r + 8][kc + tig * 2 + 8];
            }
            uint32_t rb[4][2];
            #pragma unroll
            for (int nt = 0; nt < 4; nt++) {
                const int n0 = wn * 32 + nt * 8 + grp;
                rb[nt][0] = *(const uint32_t*)&Bs[n0][kc + tig * 2];
                rb[nt][1] = *(const uint32_t*)&Bs[n0][kc + tig * 2 + 8];
            }
            #pragma unroll
            for (int mt = 0; mt < 2; mt++)
                #pragma unroll
                for (int nt = 0; nt < 4; nt++)
                    mma_f16(acc[mt][nt], ra[mt][0], ra[mt][1], ra[mt][2], ra[mt][3],
                            rb[nt][0], rb[nt][1]);
        }
        __syncthreads();
    }

    #pragma unroll
    for (int mt = 0; mt < 2; mt++) {
        #pragma unroll
        for (int nt = 0; nt < 4; nt++) {
            const int r0 = bm + wm * 32 + mt * 16 + grp;
            const int c0 = bn + wn * 32 + nt * 8 + tig * 2;
            const float b0 = bias[c0], b1 = bias[c0 + 1];
            const float v00 = acc[mt][nt][0] + b0, v01 = acc[mt][nt][1] + b1;
            const float v10 = acc[mt][nt][2] + b0, v11 = acc[mt][nt][3] + b1;
            if (Ch) {
                __half2 h0 = __floats2half2_rn(v00, v01);
                __half2 h1 = __floats2half2_rn(v10, v11);
                *(__half2*)&Ch[(size_t)r0 * N + c0]       = h0;
                *(__half2*)&Ch[(size_t)(r0 + 8) * N + c0] = h1;
            } else {
                float2 f0 = {v00, v01};
                float2 f1 = {v10, v11};
                *(float2*)&C[(size_t)r0 * N + c0]       = f0;
                *(float2*)&C[(size_t)(r0 + 8) * N + c0] = f1;
            }
        }
    }
}

// ---------------- weight transpose: W[K,N] fp32 -> Wt[N,K] fp16 ----------------
__global__ void transpose_kernel(const float* __restrict__ W, __half* __restrict__ Wt,
                                 int K, int N) {
    __shared__ float tile[32][33];
    const int n0 = blockIdx.x * 32, k0 = blockIdx.y * 32;
    for (int j = threadIdx.y; j < 32; j += 8)
        tile[j][threadIdx.x] = W[(size_t)(k0 + j) * N + n0 + threadIdx.x];
    __syncthreads();
    for (int j = threadIdx.y; j < 32; j += 8)
        Wt[(size_t)(n0 + j) * K + k0 + threadIdx.x] = __float2half(tile[threadIdx.x][j]);
}

// ---------------- precompute: smem-staged, coalesced in and out ----------------
// 128 threads / block = 16 tokens x 8 heads. Outputs point-major [pp][tm].
#define PC_TOK 16
__global__ __launch_bounds__(128)
void precompute_kernel(const float* __restrict__ refp,
                       const int*   __restrict__ spatial,
                       const int*   __restrict__ lstart) {
    __shared__ float s_soff[PC_TOK * 8 * 33];  // 32-float groups padded to 33
    __shared__ float s_attn[PC_TOK * 8 * 17];  // 16-float groups padded to 17
    __shared__ float s_ref [PC_TOK * 8];

    const int tid = threadIdx.x;
    const int t0  = blockIdx.x * PC_TOK;

    // stage soff: 16 tok x 256 floats, contiguous region -> coalesced float4
    {
        const float4* src = (const float4*)(g_soff + (size_t)t0 * DM);
        #pragma unroll
        for (int i = 0; i < 8; i++) {
            const int idx  = tid + i * 128;
            const int tm_l = idx >> 3;
            const int o4   = idx & 7;
            float4 v = src[idx];
            float* d = s_soff + tm_l * 33 + o4 * 4;
            d[0] = v.x; d[1] = v.y; d[2] = v.z; d[3] = v.w;
        }
    }
    // stage sattn: 16 tok x 128 floats
    {
        const float4* src = (const float4*)(g_sattn + (size_t)t0 * NATTN);
        #pragma unroll
        for (int i = 0; i < 4; i++) {
            const int idx  = tid + i * 128;
            const int tm_l = idx >> 2;
            const int o4   = idx & 3;
            float4 v = src[idx];
            float* d = s_attn + tm_l * 17 + o4 * 4;
            d[0] = v.x; d[1] = v.y; d[2] = v.z; d[3] = v.w;
        }
    }
    s_ref[tid] = refp[(size_t)t0 * (NL * 2) + tid];
    __syncthreads();

    const int m  = tid & 7;
    const int tl = tid >> 3;
    (void)m;
    const float* attn_l = s_attn + tid * 17;
    const float* soff_l = s_soff + tid * 33;
    const float* ref_l  = s_ref  + tl * 8;
    const size_t gtm = (size_t)t0 * 8 + tid;

    float lg[NPTS];
    float mx = -1e30f;
    #pragma unroll
    for (int i = 0; i < NPTS; i++) { lg[i] = attn_l[i]; mx = fmaxf(mx, lg[i]); }
    float ssum = 0.f;
    #pragma unroll
    for (int i = 0; i < NPTS; i++) { lg[i] = __expf(lg[i] - mx); ssum += lg[i]; }
    const float inv = 1.f / ssum;

    ushort4* opid = (ushort4*)g_pidx;
    float4*  opw  = (float4*) g_pw;

    #pragma unroll
    for (int l = 0; l < NL; l++) {
        const int   H  = spatial[l * 2 + 0];
        const int   W  = spatial[l * 2 + 1];
        const float Hf = (float)H, Wf = (float)W;
        const int start = lstart[l];
        const float rx = ref_l[l * 2 + 0];
        const float ry = ref_l[l * 2 + 1];
        #pragma unroll
        for (int p = 0; p < NP; p++) {
            const float ox = soff_l[l * (NP * 2) + p * 2 + 0];
            const float oy = soff_l[l * (NP * 2) + p * 2 + 1];
            const float x = (rx + ox / Wf) * Wf - 0.5f;
            const float y = (ry + oy / Hf) * Hf - 0.5f;
            const float x0f = floorf(x), y0f = floorf(y);
            const float fx = x - x0f, fy = y - y0f;
            const int x0 = (int)x0f, y0 = (int)y0f;
            const int x1 = x0 + 1,   y1 = y0 + 1;
            const float aw = lg[l * NP + p] * inv;

            const bool vx0 = (x0 >= 0) & (x0 < W);
            const bool vx1 = (x1 >= 0) & (x1 < W);
            const bool vy0 = (y0 >= 0) & (y0 < H);
            const bool vy1 = (y1 >= 0) & (y1 < H);

            ushort4 i4; float4 w4;
            i4.x = (vy0 && vx0) ? (unsigned short)(start + y0 * W + x0) : 0;
            i4.y = (vy0 && vx1) ? (unsigned short)(start + y0 * W + x1) : 0;
            i4.z = (vy1 && vx0) ? (unsigned short)(start + y1 * W + x0) : 0;
            i4.w = (vy1 && vx1) ? (unsigned short)(start + y1 * W + x1) : 0;
            w4.x = (vy0 && vx0) ? aw * (1.f - fx) * (1.f - fy) : 0.f;
            w4.y = (vy0 && vx1) ? aw * fx * (1.f - fy)         : 0.f;
            w4.z = (vy1 && vx0) ? aw * (1.f - fx) * fy         : 0.f;
            w4.w = (vy1 && vx1) ? aw * fx * fy                 : 0.f;

            const int pp = l * NP + p;
            opid[(size_t)pp * TMN + gtm] = i4;   // coalesced across lanes
            opw [(size_t)pp * TMN + gtm] = w4;
        }
    }
}

// ---------------- gather: one warp per (token, head); value fp16 ----------------
__global__ __launch_bounds__(256)
void sample_kernel() {
    const int warp = threadIdx.x >> 5;
    const int lane = threadIdx.x & 31;
    const int blk  = blockIdx.x;
    const int m = blk & (NH - 1);
    const int t = (blk >> 3) * 8 + warp;
    const int b = t / LEN;

    const __half* vbase = g_value + (size_t)b * LEN * DM + m * DH + lane;
    const size_t tm = (size_t)t * NH + m;
    const ushort4* pidx = (const ushort4*)g_pidx + tm;
    const float4*  pw   = (const float4*) g_pw   + tm;

    float acc = 0.f;
    #pragma unroll
    for (int pp = 0; pp < NPTS; pp++) {
        const ushort4 i4 = pidx[(size_t)pp * TMN];
        const float4  w4 = pw[(size_t)pp * TMN];
        acc += w4.x * __half2float(vbase[(int)i4.x * DM]);
        acc += w4.y * __half2float(vbase[(int)i4.y * DM]);
        acc += w4.z * __half2float(vbase[(int)i4.z * DM]);
        acc += w4.w * __half2float(vbase[(int)i4.w * DM]);
    }
    g_t[(size_t)t * DM + m * DH + lane] = acc;
}

// ---------------- launch ----------------
extern "C" void kernel_launch(void* const* d_in, const int* in_sizes, int n_in,
                              void* d_out, int out_size) {
    const float* query  = (const float*)d_in[0];
    const float* refp   = (const float*)d_in[1];
    const float* xin    = (const float*)d_in[2];
    const int*   spatial= (const int*)  d_in[3];
    const int*   lstart = (const int*)  d_in[4];
    const float* W_off  = (const float*)d_in[5];
    const float* b_off  = (const float*)d_in[6];
    const float* W_attn = (const float*)d_in[7];
    const float* b_attn = (const float*)d_in[8];
    const float* W_val  = (const float*)d_in[9];
    const float* b_val  = (const float*)d_in[10];
    const float* W_out  = (const float*)d_in[11];
    const float* b_out  = (const float*)d_in[12];
    float* out = (float*)d_out;

    __half *pvH, *wvT, *woT, *waT, *wuT;
    float *pso, *psa, *pt;
    cudaGetSymbolAddress((void**)&pvH, g_value);
    cudaGetSymbolAddress((void**)&pso, g_soff);
    cudaGetSymbolAddress((void**)&psa, g_sattn);
    cudaGetSymbolAddress((void**)&pt,  g_t);
    cudaGetSymbolAddress((void**)&wvT, g_WvalT);
    cudaGetSymbolAddress((void**)&woT, g_WoffT);
    cudaGetSymbolAddress((void**)&waT, g_WattnT);
    cudaGetSymbolAddress((void**)&wuT, g_WoutT);

    dim3 tb(32, 8);
    transpose_kernel<<<dim3(DM / 32,    DM / 32), tb>>>(W_val,  wvT, DM, DM);
    transpose_kernel<<<dim3(DM / 32,    DM / 32), tb>>>(W_off,  woT, DM, DM);
    transpose_kernel<<<dim3(NATTN / 32, DM / 32), tb>>>(W_attn, waT, DM, NATTN);
    transpose_kernel<<<dim3(DM / 32,    DM / 32), tb>>>(W_out,  wuT, DM, DM);

    const int mt = NTOK / GBM;   // 680
    f16_gemm<<<dim3(mt, DM / GBN),    256>>>(xin,   wvT, b_val,  nullptr, pvH, NTOK, DM,    DM);
    f16_gemm<<<dim3(mt, DM / GBN),    256>>>(query, woT, b_off,  pso, nullptr, NTOK, DM,    DM);
    f16_gemm<<<dim3(mt, NATTN / GBN), 256>>>(query, waT, b_attn, psa, nullptr, NTOK, NATTN, DM);

    precompute_kernel<<<NTOK / PC_TOK, 128>>>(refp, spatial, lstart);
    sample_kernel<<<NTOK, 256>>>();

    f16_gemm<<<dim3(mt, DM / GBN), 256>>>(pt, wuT, b_out, out, nullptr, NTOK, DM, DM);
}

// round 7
// speedup vs baseline: 2.6270x; 1.1946x over previous
#include <cuda_runtime.h>
#include <cuda_fp16.h>
#include <math.h>
#include <stdint.h>

// ---------------- problem constants ----------------
#define BATCH 4
#define LEN   21760
#define DM    256
#define NH    8
#define NL    4
#define NP    4
#define DH    32
#define NTOK  (BATCH * LEN)  // 87040
#define NATTN (NH * NL * NP) // 128
#define NPTS  (NL * NP)      // 16

// ---------------- scratch ----------------
__device__ __half g_value[(size_t)NTOK * DM];   // value projection, fp16
__device__ float  g_soff [(size_t)NTOK * DM];
__device__ float  g_sattn[(size_t)NTOK * NATTN];
__device__ float  g_t    [(size_t)NTOK * DM];
// transposed weights [N, K] (K-major), fp16
__device__ __half g_WvalT [DM * DM];
__device__ __half g_WoffT [DM * DM];
__device__ __half g_WattnT[NATTN * DM];
__device__ __half g_WoutT [DM * DM];

// ---------------- fp16 mma ----------------
__device__ __forceinline__ void mma_f16(float c[4],
                                        uint32_t a0, uint32_t a1, uint32_t a2, uint32_t a3,
                                        uint32_t b0, uint32_t b1) {
    asm volatile(
        "mma.sync.aligned.m16n8k16.row.col.f32.f16.f16.f32 "
        "{%0,%1,%2,%3}, {%4,%5,%6,%7}, {%8,%9}, {%0,%1,%2,%3};"
        : "+f"(c[0]), "+f"(c[1]), "+f"(c[2]), "+f"(c[3])
        : "r"(a0), "r"(a1), "r"(a2), "r"(a3), "r"(b0), "r"(b1));
}

// ---------------- fp16 mma.sync GEMM ----------------
// C[M,N] = A[M,K] @ Bt[N,K]^T + bias[N];  A fp32, Bt fp16.
// grid = (N/GBN, M/GBM): consecutive blocks share the A tile (L2 reuse).
#define GBM 128
#define GBN 64
#define GBK 32
#define HSTR (GBK + 8)   // 40 halves: conflict-free reads

__global__ __launch_bounds__(256, 2)
void f16_gemm(const float* __restrict__ A, const __half* __restrict__ Bt,
              const float* __restrict__ bias, float* __restrict__ C,
              __half* __restrict__ Ch, int M, int N, int K) {
    __shared__ __half As[GBM][HSTR];
    __shared__ __half Bs[GBN][HSTR];

    const int tid  = threadIdx.x;
    const int lane = tid & 31;
    const int wid  = tid >> 5;
    const int wm   = wid & 3;
    const int wn   = wid >> 2;
    const int bn = blockIdx.x * GBN;   // N-tile fastest -> A tile shared in L2
    const int bm = blockIdx.y * GBM;
    const int grp = lane >> 2;
    const int tig = lane & 3;

    float acc[2][4][4];
    #pragma unroll
    for (int i = 0; i < 2; i++)
        #pragma unroll
        for (int j = 0; j < 4; j++)
            #pragma unroll
            for (int r = 0; r < 4; r++) acc[i][j][r] = 0.f;

    for (int k0 = 0; k0 < K; k0 += GBK) {
        #pragma unroll
        for (int i = 0; i < 4; i++) {
            const int f   = tid + i * 256;
            const int row = f >> 3;
            const int c4  = f & 7;
            float4 v = *(const float4*)&A[(size_t)(bm + row) * K + k0 + c4 * 4];
            __half2 h01 = __floats2half2_rn(v.x, v.y);
            __half2 h23 = __floats2half2_rn(v.z, v.w);
            uint2 u;
            u.x = *(uint32_t*)&h01;
            u.y = *(uint32_t*)&h23;
            *(uint2*)&As[row][c4 * 4] = u;
        }
        {
            const int row = tid >> 2;
            const int c8  = tid & 3;
            const uint2* src = (const uint2*)&Bt[(size_t)(bn + row) * K + k0 + c8 * 8];
            uint2 u0 = src[0];
            uint2 u1 = src[1];
            *(uint2*)&Bs[row][c8 * 8]     = u0;
            *(uint2*)&Bs[row][c8 * 8 + 4] = u1;
        }
        __syncthreads();

        #pragma unroll
        for (int kc = 0; kc < GBK; kc += 16) {
            uint32_t ra[2][4];
            #pragma unroll
            for (int mt = 0; mt < 2; mt++) {
                const int r = wm * 32 + mt * 16 + grp;
                ra[mt][0] = *(const uint32_t*)&As[r    ][kc + tig * 2];
                ra[mt][1] = *(const uint32_t*)&As[r + 8][kc + tig * 2];
                ra[mt][2] = *(const uint32_t*)&As[r    ][kc + tig * 2 + 8];
                ra[mt][3] = *(const uint32_t*)&As[r + 8][kc + tig * 2 + 8];
            }
            uint32_t rb[4][2];
            #pragma unroll
            for (int nt = 0; nt < 4; nt++) {
                const int n0 = wn * 32 + nt * 8 + grp;
                rb[nt][0] = *(const uint32_t*)&Bs[n0][kc + tig * 2];
                rb[nt][1] = *(const uint32_t*)&Bs[n0][kc + tig * 2 + 8];
            }
            #pragma unroll
            for (int mt = 0; mt < 2; mt++)
                #pragma unroll
                for (int nt = 0; nt < 4; nt++)
                    mma_f16(acc[mt][nt], ra[mt][0], ra[mt][1], ra[mt][2], ra[mt][3],
                            rb[nt][0], rb[nt][1]);
        }
        __syncthreads();
    }

    #pragma unroll
    for (int mt = 0; mt < 2; mt++) {
        #pragma unroll
        for (int nt = 0; nt < 4; nt++) {
            const int r0 = bm + wm * 32 + mt * 16 + grp;
            const int c0 = bn + wn * 32 + nt * 8 + tig * 2;
            const float b0 = bias[c0], b1 = bias[c0 + 1];
            const float v00 = acc[mt][nt][0] + b0, v01 = acc[mt][nt][1] + b1;
            const float v10 = acc[mt][nt][2] + b0, v11 = acc[mt][nt][3] + b1;
            if (Ch) {
                __half2 h0 = __floats2half2_rn(v00, v01);
                __half2 h1 = __floats2half2_rn(v10, v11);
                *(__half2*)&Ch[(size_t)r0 * N + c0]       = h0;
                *(__half2*)&Ch[(size_t)(r0 + 8) * N + c0] = h1;
            } else {
                float2 f0 = {v00, v01};
                float2 f1 = {v10, v11};
                *(float2*)&C[(size_t)r0 * N + c0]       = f0;
                *(float2*)&C[(size_t)(r0 + 8) * N + c0] = f1;
            }
        }
    }
}

// ---------------- weight transpose: W[K,N] fp32 -> Wt[N,K] fp16 ----------------
__global__ void transpose_kernel(const float* __restrict__ W, __half* __restrict__ Wt,
                                 int K, int N) {
    __shared__ float tile[32][33];
    const int n0 = blockIdx.x * 32, k0 = blockIdx.y * 32;
    for (int j = threadIdx.y; j < 32; j += 8)
        tile[j][threadIdx.x] = W[(size_t)(k0 + j) * N + n0 + threadIdx.x];
    __syncthreads();
    for (int j = threadIdx.y; j < 32; j += 8)
        Wt[(size_t)(n0 + j) * K + k0 + threadIdx.x] = __float2half(tile[threadIdx.x][j]);
}

// ---------------- fused precompute + gather ----------------
// Block = 256 thr = 8 warps, covers 4 tokens x 8 heads.
// Warp w: token t0 + (w>>1), heads (w&1)*4 .. +3  (4 tm pairs).
// Phase 1 (lanes 0-3): scalar point math -> smem. Phase 2 (all lanes): gathers.
#define FB_TOK 4
#define TOKS_PER_B (LEN / FB_TOK)   // 5440 blocks per batch

__global__ __launch_bounds__(256)
void fused_sample(const float* __restrict__ refp,
                  const int*   __restrict__ spatial,
                  const int*   __restrict__ lstart) {
    __shared__ float   s_soff[8][4][36];
    __shared__ float   s_attn[8][4][20];
    __shared__ float   s_ref [8][8];
    __shared__ ushort4 s_pidx[8][4][NPTS];
    __shared__ float4  s_pw  [8][4][NPTS];

    const int tid  = threadIdx.x;
    const int w    = tid >> 5;
    const int lane = tid & 31;
    const int t0   = blockIdx.x * FB_TOK;
    const int t    = t0 + (w >> 1);          // this warp's token
    const int hb   = (w & 1) * 4;            // head base
    const int b    = blockIdx.x / TOKS_PER_B;

    // ---- stage inputs (per warp, coalesced) ----
    {
        // soff: 128 consecutive floats (4 heads x 32)
        const float4* src = (const float4*)(g_soff + (size_t)t * DM + hb * 32);
        float4 v = src[lane];
        const int j  = lane >> 3;
        const int i4 = lane & 7;
        float* d = &s_soff[w][j][i4 * 4];
        d[0] = v.x; d[1] = v.y; d[2] = v.z; d[3] = v.w;
    }
    if (lane < 16) {
        // attn: 64 consecutive floats (4 heads x 16)
        const float4* src = (const float4*)(g_sattn + (size_t)t * NATTN + hb * 16);
        float4 v = src[lane];
        const int j  = lane >> 2;
        const int i4 = lane & 3;
        float* d = &s_attn[w][j][i4 * 4];
        d[0] = v.x; d[1] = v.y; d[2] = v.z; d[3] = v.w;
    }
    if (lane < 8) s_ref[w][lane] = refp[(size_t)t * (NL * 2) + lane];
    __syncwarp();

    // ---- phase 1: lanes 0-3 compute fused (idx, weight) for one tm each ----
    if (lane < 4) {
        const float* attn_l = s_attn[w][lane];
        const float* soff_l = s_soff[w][lane];
        const float* ref_l  = s_ref[w];

        float lg[NPTS];
        float mx = -1e30f;
        #pragma unroll
        for (int i = 0; i < NPTS; i++) { lg[i] = attn_l[i]; mx = fmaxf(mx, lg[i]); }
        float ssum = 0.f;
        #pragma unroll
        for (int i = 0; i < NPTS; i++) { lg[i] = __expf(lg[i] - mx); ssum += lg[i]; }
        const float inv = 1.f / ssum;

        #pragma unroll
        for (int l = 0; l < NL; l++) {
            const int   H  = spatial[l * 2 + 0];
            const int   W  = spatial[l * 2 + 1];
            const float Hf = (float)H, Wf = (float)W;
            const int start = lstart[l];
            const float rx = ref_l[l * 2 + 0];
            const float ry = ref_l[l * 2 + 1];
            #pragma unroll
            for (int p = 0; p < NP; p++) {
                const float ox = soff_l[l * (NP * 2) + p * 2 + 0];
                const float oy = soff_l[l * (NP * 2) + p * 2 + 1];
                const float x = (rx + ox / Wf) * Wf - 0.5f;
                const float y = (ry + oy / Hf) * Hf - 0.5f;
                const float x0f = floorf(x), y0f = floorf(y);
                const float fx = x - x0f, fy = y - y0f;
                const int x0 = (int)x0f, y0 = (int)y0f;
                const int x1 = x0 + 1,   y1 = y0 + 1;
                const float aw = lg[l * NP + p] * inv;

                const bool vx0 = (x0 >= 0) & (x0 < W);
                const bool vx1 = (x1 >= 0) & (x1 < W);
                const bool vy0 = (y0 >= 0) & (y0 < H);
                const bool vy1 = (y1 >= 0) & (y1 < H);

                ushort4 i4; float4 w4;
                i4.x = (vy0 && vx0) ? (unsigned short)(start + y0 * W + x0) : 0;
                i4.y = (vy0 && vx1) ? (unsigned short)(start + y0 * W + x1) : 0;
                i4.z = (vy1 && vx0) ? (unsigned short)(start + y1 * W + x0) : 0;
                i4.w = (vy1 && vx1) ? (unsigned short)(start + y1 * W + x1) : 0;
                w4.x = (vy0 && vx0) ? aw * (1.f - fx) * (1.f - fy) : 0.f;
                w4.y = (vy0 && vx1) ? aw * fx * (1.f - fy)         : 0.f;
                w4.z = (vy1 && vx0) ? aw * (1.f - fx) * fy         : 0.f;
                w4.w = (vy1 && vx1) ? aw * fx * fy                 : 0.f;

                s_pidx[w][lane][l * NP + p] = i4;
                s_pw  [w][lane][l * NP + p] = w4;
            }
        }
    }
    __syncwarp();

    // ---- phase 2: whole warp gathers for each of its 4 tm pairs ----
    const __half* vb_b = g_value + (size_t)b * LEN * DM + lane;
    #pragma unroll
    for (int j = 0; j < 4; j++) {
        const int m = hb + j;
        const __half* vbase = vb_b + m * DH;
        float acc = 0.f;
        #pragma unroll
        for (int pp = 0; pp < NPTS; pp++) {
            const ushort4 i4 = s_pidx[w][j][pp];   // broadcast
            const float4  w4 = s_pw[w][j][pp];
            acc += w4.x * __half2float(vbase[(int)i4.x * DM]);
            acc += w4.y * __half2float(vbase[(int)i4.y * DM]);
            acc += w4.z * __half2float(vbase[(int)i4.z * DM]);
            acc += w4.w * __half2float(vbase[(int)i4.w * DM]);
        }
        g_t[(size_t)t * DM + m * DH + lane] = acc;
    }
}

// ---------------- launch ----------------
extern "C" void kernel_launch(void* const* d_in, const int* in_sizes, int n_in,
                              void* d_out, int out_size) {
    const float* query  = (const float*)d_in[0];
    const float* refp   = (const float*)d_in[1];
    const float* xin    = (const float*)d_in[2];
    const int*   spatial= (const int*)  d_in[3];
    const int*   lstart = (const int*)  d_in[4];
    const float* W_off  = (const float*)d_in[5];
    const float* b_off  = (const float*)d_in[6];
    const float* W_attn = (const float*)d_in[7];
    const float* b_attn = (const float*)d_in[8];
    const float* W_val  = (const float*)d_in[9];
    const float* b_val  = (const float*)d_in[10];
    const float* W_out  = (const float*)d_in[11];
    const float* b_out  = (const float*)d_in[12];
    float* out = (float*)d_out;

    __half *pvH, *wvT, *woT, *waT, *wuT;
    float *pso, *psa, *pt;
    cudaGetSymbolAddress((void**)&pvH, g_value);
    cudaGetSymbolAddress((void**)&pso, g_soff);
    cudaGetSymbolAddress((void**)&psa, g_sattn);
    cudaGetSymbolAddress((void**)&pt,  g_t);
    cudaGetSymbolAddress((void**)&wvT, g_WvalT);
    cudaGetSymbolAddress((void**)&woT, g_WoffT);
    cudaGetSymbolAddress((void**)&waT, g_WattnT);
    cudaGetSymbolAddress((void**)&wuT, g_WoutT);

    dim3 tb(32, 8);
    transpose_kernel<<<dim3(DM / 32,    DM / 32), tb>>>(W_val,  wvT, DM, DM);
    transpose_kernel<<<dim3(DM / 32,    DM / 32), tb>>>(W_off,  woT, DM, DM);
    transpose_kernel<<<dim3(NATTN / 32, DM / 32), tb>>>(W_attn, waT, DM, NATTN);
    transpose_kernel<<<dim3(DM / 32,    DM / 32), tb>>>(W_out,  wuT, DM, DM);

    const int mt = NTOK / GBM;   // 680
    f16_gemm<<<dim3(DM / GBN,    mt), 256>>>(xin,   wvT, b_val,  nullptr, pvH, NTOK, DM,    DM);
    f16_gemm<<<dim3(DM / GBN,    mt), 256>>>(query, woT, b_off,  pso, nullptr, NTOK, DM,    DM);
    f16_gemm<<<dim3(NATTN / GBN, mt), 256>>>(query, waT, b_attn, psa, nullptr, NTOK, NATTN, DM);

    fused_sample<<<NTOK / FB_TOK, 256>>>(refp, spatial, lstart);

    f16_gemm<<<dim3(DM / GBN, mt), 256>>>(pt, wuT, b_out, out, nullptr, NTOK, DM, DM);
}

// round 11
// speedup vs baseline: 2.8422x; 1.0819x over previous
#include <cuda_runtime.h>
#include <cuda_fp16.h>
#include <math.h>
#include <stdint.h>

// ---------------- problem constants ----------------
#define BATCH 4
#define LEN   21760
#define DM    256
#define NH    8
#define NL    4
#define NP    4
#define DH    32
#define NTOK  (BATCH * LEN)  // 87040
#define NATTN (NH * NL * NP) // 128
#define NPTS  (NL * NP)      // 16
#define NQ    (DM + NATTN)   // 384 fused query-proj width

// ---------------- scratch ----------------
__device__ __half g_value[(size_t)NTOK * DM];   // value projection, fp16
__device__ float  g_q    [(size_t)NTOK * NQ];   // [offsets(256) | attn(128)] per token
__device__ __half g_t    [(size_t)NTOK * DM];   // attention output, fp16
// transposed weights [N, K] (K-major), fp16
__device__ __half g_WvalT[DM * DM];
__device__ __half g_WqT  [NQ * DM];             // rows 0..255: W_off^T, 256..383: W_attn^T
__device__ __half g_WoutT[DM * DM];

// ---------------- fp16 mma ----------------
__device__ __forceinline__ void mma_f16(float c[4],
                                        uint32_t a0, uint32_t a1, uint32_t a2, uint32_t a3,
                                        uint32_t b0, uint32_t b1) {
    asm volatile(
        "mma.sync.aligned.m16n8k16.row.col.f32.f16.f16.f32 "
        "{%0,%1,%2,%3}, {%4,%5,%6,%7}, {%8,%9}, {%0,%1,%2,%3};"
        : "+f"(c[0]), "+f"(c[1]), "+f"(c[2]), "+f"(c[3])
        : "r"(a0), "r"(a1), "r"(a2), "r"(a3), "r"(b0), "r"(b1));
}

// ---------------- fp16 mma.sync GEMM, register-prefetch pipelined ----------------
// C[M,N] = A[M,K] @ Bt[N,K]^T + bias[N]; A fp32 (or fp16 when AHALF).
// grid = (N/GBN, M/GBM); dual bias split at nsplit (multiple of GBN).
#define GBM 128
#define GBN 64
#define GBK 32
#define HSTR (GBK + 8)   // 40 halves

template<bool AHALF>
__global__ __launch_bounds__(256, 2)
void f16_gemm(const float* __restrict__ A, const __half* __restrict__ Ah,
              const __half* __restrict__ Bt,
              const float* __restrict__ bias1, const float* __restrict__ bias2,
              int nsplit, float* __restrict__ C, __half* __restrict__ Ch,
              int M, int N, int K) {
    __shared__ __half As[GBM][HSTR];
    __shared__ __half Bs[GBN][HSTR];

    const int tid  = threadIdx.x;
    const int lane = tid & 31;
    const int wid  = tid >> 5;
    const int wm   = wid & 3;
    const int wn   = wid >> 2;
    const int bn = blockIdx.x * GBN;
    const int bm = blockIdx.y * GBM;
    const int grp = lane >> 2;
    const int tig = lane & 3;

    const float* bias = (bn < nsplit) ? bias1 : (bias2 - nsplit);

    float acc[2][4][4];
    #pragma unroll
    for (int i = 0; i < 2; i++)
        #pragma unroll
        for (int j = 0; j < 4; j++)
            #pragma unroll
            for (int r = 0; r < 4; r++) acc[i][j][r] = 0.f;

    float4 pa[4];    // fp32 A path: 4 x float4 = 16 floats/thread (4096 total)
    uint2  pah[4];   // fp16 A path: 4 x uint2  = 16 halves/thread (4096 total)
    uint2  pb[2];

    // --- prefetch chunk 0 ---
    {
        const int k0 = 0;
        if (AHALF) {
            #pragma unroll
            for (int i = 0; i < 4; i++) {
                const int f = tid + i * 256;          // 0..1023
                pah[i] = *(const uint2*)&Ah[(size_t)(bm + (f >> 3)) * K + k0 + (f & 7) * 4];
            }
        } else {
            #pragma unroll
            for (int i = 0; i < 4; i++) {
                const int f = tid + i * 256;
                pa[i] = *(const float4*)&A[(size_t)(bm + (f >> 3)) * K + k0 + (f & 7) * 4];
            }
        }
        const uint2* src = (const uint2*)&Bt[(size_t)(bn + (tid >> 2)) * K + k0 + (tid & 3) * 8];
        pb[0] = src[0];
        pb[1] = src[1];
    }

    const int nch = K / GBK;
    for (int c = 0; c < nch; c++) {
        // --- store prefetched regs to smem ---
        if (AHALF) {
            #pragma unroll
            for (int i = 0; i < 4; i++) {
                const int f = tid + i * 256;
                *(uint2*)&As[f >> 3][(f & 7) * 4] = pah[i];
            }
        } else {
            #pragma unroll
            for (int i = 0; i < 4; i++) {
                const int f = tid + i * 256;
                __half2 h01 = __floats2half2_rn(pa[i].x, pa[i].y);
                __half2 h23 = __floats2half2_rn(pa[i].z, pa[i].w);
                uint2 u;
                u.x = *(uint32_t*)&h01;
                u.y = *(uint32_t*)&h23;
                *(uint2*)&As[f >> 3][(f & 7) * 4] = u;
            }
        }
        *(uint2*)&Bs[tid >> 2][(tid & 3) * 8]     = pb[0];
        *(uint2*)&Bs[tid >> 2][(tid & 3) * 8 + 4] = pb[1];
        __syncthreads();

        // --- issue next chunk's global loads early ---
        if (c + 1 < nch) {
            const int k0 = (c + 1) * GBK;
            if (AHALF) {
                #pragma unroll
                for (int i = 0; i < 4; i++) {
                    const int f = tid + i * 256;
                    pah[i] = *(const uint2*)&Ah[(size_t)(bm + (f >> 3)) * K + k0 + (f & 7) * 4];
                }
            } else {
                #pragma unroll
                for (int i = 0; i < 4; i++) {
                    const int f = tid + i * 256;
                    pa[i] = *(const float4*)&A[(size_t)(bm + (f >> 3)) * K + k0 + (f & 7) * 4];
                }
            }
            const uint2* src = (const uint2*)&Bt[(size_t)(bn + (tid >> 2)) * K + k0 + (tid & 3) * 8];
            pb[0] = src[0];
            pb[1] = src[1];
        }

        // --- compute on current smem ---
        #pragma unroll
        for (int kc = 0; kc < GBK; kc += 16) {
            uint32_t ra[2][4];
            #pragma unroll
            for (int mt = 0; mt < 2; mt++) {
                const int r = wm * 32 + mt * 16 + grp;
                ra[mt][0] = *(const uint32_t*)&As[r    ][kc + tig * 2];
                ra[mt][1] = *(const uint32_t*)&As[r + 8][kc + tig * 2];
                ra[mt][2] = *(const uint32_t*)&As[r    ][kc + tig * 2 + 8];
                ra[mt][3] = *(const uint32_t*)&As[r + 8][kc + tig * 2 + 8];
            }
            uint32_t rb[4][2];
            #pragma unroll
            for (int nt = 0; nt < 4; nt++) {
                const int n0 = wn * 32 + nt * 8 + grp;
                rb[nt][0] = *(const uint32_t*)&Bs[n0][kc + tig * 2];
                rb[nt][1] = *(const uint32_t*)&Bs[n0][kc + tig * 2 + 8];
            }
            #pragma unroll
            for (int mt = 0; mt < 2; mt++)
                #pragma unroll
                for (int nt = 0; nt < 4; nt++)
                    mma_f16(acc[mt][nt], ra[mt][0], ra[mt][1], ra[mt][2], ra[mt][3],
                            rb[nt][0], rb[nt][1]);
        }
        __syncthreads();
    }

    #pragma unroll
    for (int mt = 0; mt < 2; mt++) {
        #pragma unroll
        for (int nt = 0; nt < 4; nt++) {
            const int r0 = bm + wm * 32 + mt * 16 + grp;
            const int c0 = bn + wn * 32 + nt * 8 + tig * 2;
            const float b0 = bias[c0], b1 = bias[c0 + 1];
            const float v00 = acc[mt][nt][0] + b0, v01 = acc[mt][nt][1] + b1;
            const float v10 = acc[mt][nt][2] + b0, v11 = acc[mt][nt][3] + b1;
            if (Ch) {
                __half2 h0 = __floats2half2_rn(v00, v01);
                __half2 h1 = __floats2half2_rn(v10, v11);
                *(__half2*)&Ch[(size_t)r0 * N + c0]       = h0;
                *(__half2*)&Ch[(size_t)(r0 + 8) * N + c0] = h1;
            } else {
                float2 f0 = {v00, v01};
                float2 f1 = {v10, v11};
                *(float2*)&C[(size_t)r0 * N + c0]       = f0;
                *(float2*)&C[(size_t)(r0 + 8) * N + c0] = f1;
            }
        }
    }
}

// ---------------- all 4 weight transposes in one launch ----------------
__global__ void transpose_all(const float* __restrict__ Wv, const float* __restrict__ Wo,
                              const float* __restrict__ Wa, const float* __restrict__ Wu) {
    __shared__ float tile[32][33];
    const int z = blockIdx.z;
    const float* W;
    __half* Wt;
    int N;
    if (z == 0)      { W = Wv; Wt = g_WvalT;                 N = DM; }
    else if (z == 1) { W = Wo; Wt = g_WqT;                   N = DM; }
    else if (z == 2) { W = Wa; Wt = g_WqT + (size_t)DM * DM; N = NATTN; }
    else             { W = Wu; Wt = g_WoutT;                 N = DM; }

    const int n0 = blockIdx.x * 32, k0 = blockIdx.y * 32;
    if (n0 >= N) return;
    for (int j = threadIdx.y; j < 32; j += 8)
        tile[j][threadIdx.x] = W[(size_t)(k0 + j) * N + n0 + threadIdx.x];
    __syncthreads();
    for (int j = threadIdx.y; j < 32; j += 8)
        Wt[(size_t)(n0 + j) * DM + k0 + threadIdx.x] = __float2half(tile[threadIdx.x][j]);
}

// ---------------- fused precompute + gather ----------------
#define FB_TOK 4
#define TOKS_PER_B (LEN / FB_TOK)

__global__ __launch_bounds__(256)
void fused_sample(const float* __restrict__ refp,
                  const int*   __restrict__ spatial,
                  const int*   __restrict__ lstart) {
    __shared__ float   s_soff[8][4][36];
    __shared__ float   s_attn[8][4][20];
    __shared__ float   s_ref [8][8];
    __shared__ ushort4 s_pidx[8][4][NPTS];
    __shared__ float4  s_pw  [8][4][NPTS];

    const int tid  = threadIdx.x;
    const int w    = tid >> 5;
    const int lane = tid & 31;
    const int t0   = blockIdx.x * FB_TOK;
    const int t    = t0 + (w >> 1);
    const int hb   = (w & 1) * 4;
    const int b    = blockIdx.x / TOKS_PER_B;

    {
        const float4* src = (const float4*)(g_q + (size_t)t * NQ + hb * 32);
        float4 v = src[lane];
        const int j  = lane >> 3;
        const int i4 = lane & 7;
        float* d = &s_soff[w][j][i4 * 4];
        d[0] = v.x; d[1] = v.y; d[2] = v.z; d[3] = v.w;
    }
    if (lane < 16) {
        const float4* src = (const float4*)(g_q + (size_t)t * NQ + DM + hb * 16);
        float4 v = src[lane];
        const int j  = lane >> 2;
        const int i4 = lane & 3;
        float* d = &s_attn[w][j][i4 * 4];
        d[0] = v.x; d[1] = v.y; d[2] = v.z; d[3] = v.w;
    }
    if (lane < 8) s_ref[w][lane] = refp[(size_t)t * (NL * 2) + lane];
    __syncwarp();

    if (lane < 4) {
        const float* attn_l = s_attn[w][lane];
        const float* soff_l = s_soff[w][lane];
        const float* ref_l  = s_ref[w];

        float lg[NPTS];
        float mx = -1e30f;
        #pragma unroll
        for (int i = 0; i < NPTS; i++) { lg[i] = attn_l[i]; mx = fmaxf(mx, lg[i]); }
        float ssum = 0.f;
        #pragma unroll
        for (int i = 0; i < NPTS; i++) { lg[i] = __expf(lg[i] - mx); ssum += lg[i]; }
        const float inv = 1.f / ssum;

        #pragma unroll
        for (int l = 0; l < NL; l++) {
            const int   H  = spatial[l * 2 + 0];
            const int   W  = spatial[l * 2 + 1];
            const float Hf = (float)H, Wf = (float)W;
            const int start = lstart[l];
            const float rx = ref_l[l * 2 + 0];
            const float ry = ref_l[l * 2 + 1];
            #pragma unroll
            for (int p = 0; p < NP; p++) {
                const float ox = soff_l[l * (NP * 2) + p * 2 + 0];
                const float oy = soff_l[l * (NP * 2) + p * 2 + 1];
                const float x = (rx + ox / Wf) * Wf - 0.5f;
                const float y = (ry + oy / Hf) * Hf - 0.5f;
                const float x0f = floorf(x), y0f = floorf(y);
                const float fx = x - x0f, fy = y - y0f;
                const int x0 = (int)x0f, y0 = (int)y0f;
                const int x1 = x0 + 1,   y1 = y0 + 1;
                const float aw = lg[l * NP + p] * inv;

                const bool vx0 = (x0 >= 0) & (x0 < W);
                const bool vx1 = (x1 >= 0) & (x1 < W);
                const bool vy0 = (y0 >= 0) & (y0 < H);
                const bool vy1 = (y1 >= 0) & (y1 < H);

                ushort4 i4; float4 w4;
                i4.x = (vy0 && vx0) ? (unsigned short)(start + y0 * W + x0) : 0;
                i4.y = (vy0 && vx1) ? (unsigned short)(start + y0 * W + x1) : 0;
                i4.z = (vy1 && vx0) ? (unsigned short)(start + y1 * W + x0) : 0;
                i4.w = (vy1 && vx1) ? (unsigned short)(start + y1 * W + x1) : 0;
                w4.x = (vy0 && vx0) ? aw * (1.f - fx) * (1.f - fy) : 0.f;
                w4.y = (vy0 && vx1) ? aw * fx * (1.f - fy)         : 0.f;
                w4.z = (vy1 && vx0) ? aw * (1.f - fx) * fy         : 0.f;
                w4.w = (vy1 && vx1) ? aw * fx * fy                 : 0.f;

                s_pidx[w][lane][l * NP + p] = i4;
                s_pw  [w][lane][l * NP + p] = w4;
            }
        }
    }
    __syncwarp();

    const __half* vb_b = g_value + (size_t)b * LEN * DM + lane;
    #pragma unroll
    for (int j = 0; j < 4; j++) {
        const int m = hb + j;
        const __half* vbase = vb_b + m * DH;
        float acc = 0.f;
        #pragma unroll
        for (int pp = 0; pp < NPTS; pp++) {
            const ushort4 i4 = s_pidx[w][j][pp];
            const float4  w4 = s_pw[w][j][pp];
            acc += w4.x * __half2float(vbase[(int)i4.x * DM]);
            acc += w4.y * __half2float(vbase[(int)i4.y * DM]);
            acc += w4.z * __half2float(vbase[(int)i4.z * DM]);
            acc += w4.w * __half2float(vbase[(int)i4.w * DM]);
        }
        g_t[(size_t)t * DM + m * DH + lane] = __float2half(acc);
    }
}

// ---------------- launch ----------------
extern "C" void kernel_launch(void* const* d_in, const int* in_sizes, int n_in,
                              void* d_out, int out_size) {
    const float* query  = (const float*)d_in[0];
    const float* refp   = (const float*)d_in[1];
    const float* xin    = (const float*)d_in[2];
    const int*   spatial= (const int*)  d_in[3];
    const int*   lstart = (const int*)  d_in[4];
    const float* W_off  = (const float*)d_in[5];
    const float* b_off  = (const float*)d_in[6];
    const float* W_attn = (const float*)d_in[7];
    const float* b_attn = (const float*)d_in[8];
    const float* W_val  = (const float*)d_in[9];
    const float* b_val  = (const float*)d_in[10];
    const float* W_out  = (const float*)d_in[11];
    const float* b_out  = (const float*)d_in[12];
    float* out = (float*)d_out;

    __half *pvH, *ptH, *wvT, *wqT, *wuT;
    float *pq;
    cudaGetSymbolAddress((void**)&pvH, g_value);
    cudaGetSymbolAddress((void**)&pq,  g_q);
    cudaGetSymbolAddress((void**)&ptH, g_t);
    cudaGetSymbolAddress((void**)&wvT, g_WvalT);
    cudaGetSymbolAddress((void**)&wqT, g_WqT);
    cudaGetSymbolAddress((void**)&wuT, g_WoutT);

    transpose_all<<<dim3(8, 8, 4), dim3(32, 8)>>>(W_val, W_off, W_attn, W_out);

    const int mt = NTOK / GBM;   // 680
    const int BIG = 1 << 30;
    // value projection -> fp16
    f16_gemm<false><<<dim3(DM / GBN, mt), 256>>>(xin, nullptr, wvT, b_val, b_val, BIG,
                                                 nullptr, pvH, NTOK, DM, DM);
    // fused offsets+attn projection (N=384, dual bias)
    f16_gemm<false><<<dim3(NQ / GBN, mt), 256>>>(query, nullptr, wqT, b_off, b_attn, DM,
                                                 pq, nullptr, NTOK, NQ, DM);

    fused_sample<<<NTOK / FB_TOK, 256>>>(refp, spatial, lstart);

    // output projection, fp16 A
    f16_gemm<true><<<dim3(DM / GBN, mt), 256>>>(nullptr, ptH, wuT, b_out, b_out, BIG,
                                                out, nullptr, NTOK, DM, DM);
}